// round 17
// baseline (speedup 1.0000x reference)
#include <cuda_runtime.h>
#include <cuda_bf16.h>
#include <cstdint>
#include <cstddef>

#define Bsz 64
#define Tlen 512
#define HID 1024
#define VOC 128
#define GRID 128
#define CPC 8
#define NTHR 512
#define FSTRIDE 32
#define KC 128
#define XSTR 12

// ---- smem byte offsets ----
#define BAo   0u          // B_A [1024 k][40 n-stride] bf16 (80 B rows)   81920
#define BBo   81920u      // B_B [1024 k][24 n-stride] bf16 (48 B rows)   49152
#define ASLo  131072u     // A ring: 2 slots x 128 rows x 272 B           69632
#define DSMo  200704u     // D staging 128 x 33 fp32                      16896
#define XGo   217600u     // x-gather staging 3*64*12 fp32                 9216
#define HSTo  226816u     // h/rh bf16 staging 128 x 8                     2048
#define TOKo  228864u     // 64 ints
#define BIASo 229120u     // 24 floats
#define SMSZ  229248u

__device__ float g_hist[(size_t)Tlen * HID * Bsz];
__device__ __align__(16) __nv_bfloat16 g_hA[128 * HID];   // rows 0-63 hi, 64-127 lo
__device__ __align__(16) __nv_bfloat16 g_rhA[128 * HID];
__device__ __align__(128) unsigned g_flags[GRID * FSTRIDE];

__device__ __forceinline__ float sigmoidf_(float x) { return 1.0f / (1.0f + __expf(-x)); }

__device__ __forceinline__ uint32_t smem_u32(const void* p) {
    uint32_t a;
    asm("{ .reg .u64 t; cvta.to.shared.u64 t, %1; cvt.u32.u64 %0, t; }" : "=r"(a) : "l"(p));
    return a;
}

__device__ __forceinline__ void gbar(unsigned stamp) {
    __syncthreads();
    if (threadIdx.x == 0)
        asm volatile("st.global.release.gpu.u32 [%0], %1;"
                     :: "l"(&g_flags[blockIdx.x * FSTRIDE]), "r"(stamp) : "memory");
    if (threadIdx.x < GRID) {
        unsigned v;
        do {
            asm volatile("ld.global.acquire.gpu.u32 %0, [%1];"
                         : "=r"(v) : "l"(&g_flags[threadIdx.x * FSTRIDE]) : "memory");
        } while (v < stamp);
    }
    __syncthreads();
}

// fill one A chunk: 128 rows x 128 k bf16 (256 B/row) into padded (272 B) slot
__device__ __forceinline__ void fill_tile(uint32_t sl, const __nv_bfloat16* g,
                                          int ck, int tid) {
    int r = tid >> 2;
    int u0 = (tid & 3) * 4;
    const char* gp = (const char*)(g + (size_t)r * HID + ck * 128) + u0 * 16;
    uint32_t sp = sl + (uint32_t)r * 272u + (uint32_t)u0 * 16u;
    #pragma unroll
    for (int i = 0; i < 4; ++i)
        asm volatile("cp.async.cg.shared.global [%0], [%1], 16;"
                     :: "r"(sp + i * 16), "l"(gp + i * 16) : "memory");
    asm volatile("cp.async.commit_group;" ::: "memory");
}

#define MMA(acc, A0, A1, A2, A3, B0, B1)                                        \
    asm volatile("mma.sync.aligned.m16n8k16.row.col.f32.bf16.bf16.f32 "         \
                 "{%0,%1,%2,%3}, {%4,%5,%6,%7}, {%8,%9}, {%0,%1,%2,%3};"        \
                 : "+f"((acc)[0]), "+f"((acc)[1]), "+f"((acc)[2]), "+f"((acc)[3]) \
                 : "r"(A0), "r"(A1), "r"(A2), "r"(A3), "r"(B0), "r"(B1))

__global__ void __launch_bounds__(NTHR, 1)
gru_step_kernel(const int* __restrict__ X,
                const float* __restrict__ Wr_x, const float* __restrict__ b_r,
                const float* __restrict__ Wz_x, const float* __restrict__ b_z,
                const float* __restrict__ Wh_x, const float* __restrict__ b_h,
                const float* __restrict__ Wr_h, const float* __restrict__ Wz_h,
                const float* __restrict__ Wh_h,
                const float* __restrict__ W_o,  const float* __restrict__ b_o,
                float* __restrict__ out)
{
    extern __shared__ char smc[];
    const uint32_t sb = smem_u32(smc);
    float* dsm  = (float*)(smc + DSMo);
    float* xg   = (float*)(smc + XGo);
    float* bias = (float*)(smc + BIASo);
    int*   tok  = (int*)(smc + TOKo);
    __nv_bfloat16* hst = (__nv_bfloat16*)(smc + HSTo);

    const int tid = threadIdx.x, wid = tid >> 5, lid = tid & 31;
    const int cb = blockIdx.x, c0 = cb * CPC;
    unsigned bstamp = g_flags[cb * FSTRIDE];

    // ---- weight B-tiles: cols 0-15 = hi{r|z}, 16-31 = lo{r|z}; phase B 0-7 hi, 8-15 lo
    for (int idx = tid; idx < 32 * HID; idx += NTHR) {
        int n = idx & 31, k = idx >> 5, nn = n & 15;
        float w = (nn < 8) ? Wr_h[k * HID + c0 + nn] : Wz_h[k * HID + c0 + nn - 8];
        __nv_bfloat16 hi = __float2bfloat16(w);
        __nv_bfloat16 v = (n < 16) ? hi : __float2bfloat16(w - __bfloat162float(hi));
        *(__nv_bfloat16*)(smc + BAo + (uint32_t)k * 80u + (uint32_t)n * 2u) = v;
    }
    for (int idx = tid; idx < 16 * HID; idx += NTHR) {
        int n = idx & 15, k = idx >> 4;
        float w = Wh_h[k * HID + c0 + (n & 7)];
        __nv_bfloat16 hi = __float2bfloat16(w);
        __nv_bfloat16 v = (n < 8) ? hi : __float2bfloat16(w - __bfloat162float(hi));
        *(__nv_bfloat16*)(smc + BBo + (uint32_t)k * 48u + (uint32_t)n * 2u) = v;
    }
    if (tid < 8)       bias[tid] = b_r[c0 + tid];
    else if (tid < 16) bias[tid] = b_z[c0 + tid - 8];
    else if (tid < 24) bias[tid] = b_h[c0 + tid - 16];

    const int b = tid & 63, cq = tid >> 6, ccol = c0 + cq;
    float h_prev = 0.0f, zv_reg = 0.0f;
    g_hA[b * HID + ccol] = __float2bfloat16(0.0f);
    g_hA[(64 + b) * HID + ccol] = __float2bfloat16(0.0f);
    if (tid < Bsz) tok[tid] = X[tid * Tlen];

    gbar(++bstamp);

    // ---- mma mappings: 16 warps = 8 m-tiles x 2 n-groups ----
    const int wm = wid & 7, wn = wid >> 3;
    const uint32_t sl0 = sb + ASLo, sl1 = sb + ASLo + 34816u;
    const uint32_t aoff = (uint32_t)(wm * 16 + (lid & 15)) * 272u
                        + (uint32_t)(lid >> 4) * 16u;
    const int bkr = lid & 15;
    // phase A B lanes: 0-15 -> n-tile wn*2, 16-31 -> n-tile wn*2+1
    const uint32_t bbA = sb + BAo + (uint32_t)bkr * 80u
                       + (uint32_t)(wn * 2 + (lid >> 4)) * 16u;
    const uint32_t bbB = sb + BBo + (uint32_t)bkr * 48u + (uint32_t)wn * 16u;

    for (int t = 0; t < Tlen; ++t) {
        if (tid < 384) {
            int m = tid >> 7, r = tid & 127, gb = r >> 1, hf = (r & 1) * 4;
            const float* W = (m == 0) ? Wr_x : (m == 1) ? Wz_x : Wh_x;
            float4 v = *(const float4*)&W[tok[gb] * HID + c0 + hf];
            *(float4*)&xg[m * Bsz * XSTR + gb * XSTR + hf] = v;
        }

        // ============ Phase A: D[128,32] = [h_hi;h_lo] @ [Wrz_hi|Wrz_lo] ========
        float ar[8];
        #pragma unroll
        for (int i = 0; i < 8; ++i) ar[i] = 0.0f;
        fill_tile(sl0, g_hA, 0, tid);
        #pragma unroll 1
        for (int ck = 0; ck < 8; ++ck) {
            asm volatile("cp.async.wait_group 0;" ::: "memory");
            __syncthreads();
            if (ck + 1 < 8) fill_tile((ck & 1) ? sl0 : sl1, g_hA, ck + 1, tid);
            uint32_t sa  = ((ck & 1) ? sl1 : sl0) + aoff;
            uint32_t bkb = bbA + (uint32_t)(ck * 128) * 80u;
            #pragma unroll
            for (int ks = 0; ks < 8; ++ks) {
                uint32_t a0, a1, a2, a3, b0, b1, b2, b3;
                asm volatile("ldmatrix.sync.aligned.m8n8.x4.shared.b16 "
                             "{%0,%1,%2,%3}, [%4];"
                             : "=r"(a0), "=r"(a1), "=r"(a2), "=r"(a3)
                             : "r"(sa + (uint32_t)ks * 32u));
                asm volatile("ldmatrix.sync.aligned.m8n8.x4.trans.shared.b16 "
                             "{%0,%1,%2,%3}, [%4];"
                             : "=r"(b0), "=r"(b1), "=r"(b2), "=r"(b3)
                             : "r"(bkb + (uint32_t)(ks * 16) * 80u));
                MMA(ar,     a0, a1, a2, a3, b0, b1);
                MMA((ar+4), a0, a1, a2, a3, b2, b3);
            }
        }
        {   // D -> dsm (stride 33)
            int r0 = wm * 16 + (lid >> 2), cA = (lid & 3) * 2;
            int n0 = (wn * 2) * 8, n1 = n0 + 8;
            dsm[r0 * 33 + n0 + cA]           = ar[0];
            dsm[r0 * 33 + n0 + cA + 1]       = ar[1];
            dsm[(r0 + 8) * 33 + n0 + cA]     = ar[2];
            dsm[(r0 + 8) * 33 + n0 + cA + 1] = ar[3];
            dsm[r0 * 33 + n1 + cA]           = ar[4];
            dsm[r0 * 33 + n1 + cA + 1]       = ar[5];
            dsm[(r0 + 8) * 33 + n1 + cA]     = ar[6];
            dsm[(r0 + 8) * 33 + n1 + cA + 1] = ar[7];
        }
        __syncthreads();
        {   // gates + r*h ; cols: 0-7 r_hi, 8-15 z_hi, 16-23 r_lo, 24-31 z_lo
            float sR = dsm[b * 33 + cq] + dsm[b * 33 + 16 + cq]
                     + dsm[(64 + b) * 33 + cq];
            float sZ = dsm[b * 33 + 8 + cq] + dsm[b * 33 + 24 + cq]
                     + dsm[(64 + b) * 33 + 8 + cq];
            float rv = sigmoidf_(sR + xg[b * XSTR + cq] + bias[cq]);
            zv_reg   = sigmoidf_(sZ + xg[Bsz * XSTR + b * XSTR + cq] + bias[8 + cq]);
            float rh = rv * h_prev;
            __nv_bfloat16 hi = __float2bfloat16(rh);
            hst[b * 8 + cq] = hi;
            hst[(64 + b) * 8 + cq] = __float2bfloat16(rh - __bfloat162float(hi));
        }
        __syncthreads();
        if (tid < 128)   // coalesced 16B rows -> global rh
            *(uint4*)&g_rhA[tid * HID + c0] = *(const uint4*)(smc + HSTo + tid * 16);
        gbar(++bstamp);

        // ============ Phase B: D[128,16] = [rh_hi;rh_lo] @ [Wh_hi|Wh_lo] ========
        float ab[4];
        #pragma unroll
        for (int i = 0; i < 4; ++i) ab[i] = 0.0f;
        fill_tile(sl0, g_rhA, 0, tid);
        #pragma unroll 1
        for (int ck = 0; ck < 8; ++ck) {
            asm volatile("cp.async.wait_group 0;" ::: "memory");
            __syncthreads();
            if (ck + 1 < 8) fill_tile((ck & 1) ? sl0 : sl1, g_rhA, ck + 1, tid);
            uint32_t sa  = ((ck & 1) ? sl1 : sl0) + aoff;
            uint32_t bkb = bbB + (uint32_t)(ck * 128) * 48u;
            #pragma unroll
            for (int ks = 0; ks < 8; ++ks) {
                uint32_t a0, a1, a2, a3, b0, b1;
                asm volatile("ldmatrix.sync.aligned.m8n8.x4.shared.b16 "
                             "{%0,%1,%2,%3}, [%4];"
                             : "=r"(a0), "=r"(a1), "=r"(a2), "=r"(a3)
                             : "r"(sa + (uint32_t)ks * 32u));
                asm volatile("ldmatrix.sync.aligned.m8n8.x2.trans.shared.b16 "
                             "{%0,%1}, [%2];"
                             : "=r"(b0), "=r"(b1)
                             : "r"(bkb + (uint32_t)(ks * 16) * 48u));
                MMA(ab, a0, a1, a2, a3, b0, b1);
            }
        }
        {
            int r0 = wm * 16 + (lid >> 2), cA = (lid & 3) * 2;
            int n0 = wn * 8;
            dsm[r0 * 33 + n0 + cA]           = ab[0];
            dsm[r0 * 33 + n0 + cA + 1]       = ab[1];
            dsm[(r0 + 8) * 33 + n0 + cA]     = ab[2];
            dsm[(r0 + 8) * 33 + n0 + cA + 1] = ab[3];
        }
        __syncthreads();
        {   // h update; cols 0-7 hi, 8-15 lo
            float sH = dsm[b * 33 + cq] + dsm[b * 33 + 8 + cq]
                     + dsm[(64 + b) * 33 + cq];
            float ht = tanhf(sH + xg[2 * Bsz * XSTR + b * XSTR + cq] + bias[16 + cq]);
            float hn = zv_reg * h_prev + (1.0f - zv_reg) * ht;
            h_prev = hn;
            __nv_bfloat16 hi = __float2bfloat16(hn);
            hst[b * 8 + cq] = hi;
            hst[(64 + b) * 8 + cq] = __float2bfloat16(hn - __bfloat162float(hi));
            g_hist[((size_t)t * HID + ccol) * Bsz + b] = hn;
        }
        __syncthreads();
        if (tid < 128)
            *(uint4*)&g_hA[tid * HID + c0] = *(const uint4*)(smc + HSTo + tid * 16);
        if (tid < Bsz) {
            int tn = (t + 1 < Tlen) ? t + 1 : t;
            tok[tid] = X[tid * Tlen + tn];
        }
        gbar(++bstamp);
    }

    // ---------------- fused output head: 4 timesteps per CTA ----------------
    {
        float* swo = (float*)smc;
        const int hb = tid >> 3;
        const int v0 = (tid & 7) * 16;
        for (int tt = 0; tt < 4; ++tt) {
            const int t = cb * 4 + tt;
            float acc[16];
            #pragma unroll
            for (int i = 0; i < 16; ++i) acc[i] = 0.0f;
            for (int kc = 0; kc < HID; kc += KC) {
                __syncthreads();
                for (int i = tid; i < KC * VOC; i += NTHR)
                    swo[i] = W_o[kc * VOC + i];
                __syncthreads();
                const float* hp = g_hist + ((size_t)t * HID + kc) * Bsz + hb;
                #pragma unroll 1
                for (int kk = 0; kk < KC; kk += 8) {
                    float hv[8];
                    #pragma unroll
                    for (int u = 0; u < 8; ++u) hv[u] = __ldcg(hp + (kk + u) * Bsz);
                    #pragma unroll
                    for (int u = 0; u < 8; ++u) {
                        const float* wrow = swo + (kk + u) * VOC + v0;
                        #pragma unroll
                        for (int q = 0; q < 16; ++q)
                            acc[q] = fmaf(hv[u], wrow[q], acc[q]);
                    }
                }
            }
            float* op = out + ((size_t)hb * Tlen + t) * VOC + v0;
            #pragma unroll
            for (int q = 0; q < 16; ++q) op[q] = acc[q] + b_o[v0 + q];
        }
    }
}

extern "C" void kernel_launch(void* const* d_in, const int* in_sizes, int n_in,
                              void* d_out, int out_size)
{
    const int*   X    = (const int*)  d_in[0];
    const float* Wr_x = (const float*)d_in[1];
    const float* Wr_h = (const float*)d_in[2];
    const float* b_r  = (const float*)d_in[3];
    const float* Wz_x = (const float*)d_in[4];
    const float* Wz_h = (const float*)d_in[5];
    const float* b_z  = (const float*)d_in[6];
    const float* Wh_x = (const float*)d_in[7];
    const float* Wh_h = (const float*)d_in[8];
    const float* b_h  = (const float*)d_in[9];
    const float* W_o  = (const float*)d_in[10];
    const float* b_o  = (const float*)d_in[11];
    float* out = (float*)d_out;

    cudaFuncSetAttribute(gru_step_kernel,
                         cudaFuncAttributeMaxDynamicSharedMemorySize, (int)SMSZ);
    gru_step_kernel<<<GRID, NTHR, SMSZ>>>(X, Wr_x, b_r, Wz_x, b_z, Wh_x, b_h,
                                          Wr_h, Wz_h, Wh_h, W_o, b_o, out);
}